// round 14
// baseline (speedup 1.0000x reference)
#include <cuda_runtime.h>
#include <cuda_bf16.h>
#include <cstdint>

// Off-diagonal Gram sum via:
//   (1/D) sum_d [ (sum_b x2[b,d])^2 - sum_b x2[b,d]^2 ],  x2 = x*x.
//
// FINAL (converged, R10/R13 config): 294 CTAs x 512 thr (32 warps/SM),
// warp-internal 4-way b-split (lane = 8q + c), 8 staged LDG.128/thread
// at compile-time-constant strides, packed f32x2 inner math, shfl-only
// s-recombine, single fused kernel with last-block finalize.
//
// 13 rounds established a hard ~8.7us bench floor (graph-replay/launch
// overhead + clock-unramped hot phase at the per-SM memory request-rate
// cap). This config hit the floor 4x with the best cold profile
// (ncu 7.97us, DRAM 30.7%, occ 36%). The headline win was algebraic:
// restructuring the B x B Gram einsum into a single O(B*D) streaming
// pass (s = sum_b x^2 per column; result = sum_d s^2 - sum x^4).

#define B_ROWS 32
#define THREADS 512
#define QROWS 8
#define D4_CONST 37632          // 150528 / 4

__device__ double g_acc = 0.0;
__device__ unsigned int g_count = 0;

__device__ __forceinline__ unsigned long long pk2(float lo, float hi) {
    unsigned long long r;
    asm("mov.b64 %0, {%1, %2};" : "=l"(r) : "f"(lo), "f"(hi));
    return r;
}
__device__ __forceinline__ void upk2(unsigned long long v, float& lo, float& hi) {
    asm("mov.b64 {%0, %1}, %2;" : "=f"(lo), "=f"(hi) : "l"(v));
}
__device__ __forceinline__ unsigned long long mul2(unsigned long long a, unsigned long long b) {
    unsigned long long r;
    asm("mul.rn.f32x2 %0, %1, %2;" : "=l"(r) : "l"(a), "l"(b));
    return r;
}
__device__ __forceinline__ unsigned long long add2(unsigned long long a, unsigned long long b) {
    unsigned long long r;
    asm("add.rn.f32x2 %0, %1, %2;" : "=l"(r) : "l"(a), "l"(b));
    return r;
}
__device__ __forceinline__ unsigned long long fma2(unsigned long long a, unsigned long long b,
                                                   unsigned long long c) {
    unsigned long long r;
    asm("fma.rn.f32x2 %0, %1, %2, %3;" : "=l"(r) : "l"(a), "l"(b), "l"(c));
    return r;
}

template <int D4>
__device__ __forceinline__ void ortho_body(const float4* __restrict__ in,
                                           float* __restrict__ out,
                                           double inv_d, int nblocks) {
    const int tid  = threadIdx.x;
    const int lane = tid & 31;
    const int q    = lane >> 3;                       // b-quarter 0..3
    const int c    = lane & 7;                        // column within warp
    const int wid  = tid >> 5;
    const int gw   = blockIdx.x * (THREADS / 32) + wid;
    const int col  = gw * 8 + c;

    // 8 staged loads at compile-time-constant offsets from one base
    const float4* p = in + (size_t)(q * QROWS) * D4 + col;
    float4 v[QROWS];
    #pragma unroll
    for (int j = 0; j < QROWS; j++)
        v[j] = p[(size_t)j * D4];

    unsigned long long s01 = 0ull, s23 = 0ull, t01 = 0ull, t23 = 0ull;
    #pragma unroll
    for (int j = 0; j < QROWS; j++) {
        unsigned long long v01 = pk2(v[j].x, v[j].y);
        unsigned long long v23 = pk2(v[j].z, v[j].w);
        unsigned long long a01 = mul2(v01, v01);
        unsigned long long a23 = mul2(v23, v23);
        s01 = add2(s01, a01);
        s23 = add2(s23, a23);
        t01 = fma2(a01, a01, t01);
        t23 = fma2(a23, a23, t23);
    }

    float sx, sy, sz, sw, tx, ty, tz, tw;
    upk2(s01, sx, sy); upk2(s23, sz, sw);
    upk2(t01, tx, ty); upk2(t23, tz, tw);
    float tsum = (tx + ty) + (tz + tw);

    // recombine s across the 4 b-quarters (lanes c, c+8, c+16, c+24)
    sx += __shfl_xor_sync(0xFFFFFFFFu, sx, 8);
    sx += __shfl_xor_sync(0xFFFFFFFFu, sx, 16);
    sy += __shfl_xor_sync(0xFFFFFFFFu, sy, 8);
    sy += __shfl_xor_sync(0xFFFFFFFFu, sy, 16);
    sz += __shfl_xor_sync(0xFFFFFFFFu, sz, 8);
    sz += __shfl_xor_sync(0xFFFFFFFFu, sz, 16);
    sw += __shfl_xor_sync(0xFFFFFFFFu, sw, 8);
    sw += __shfl_xor_sync(0xFFFFFFFFu, sw, 16);

    float val = -tsum;
    if (q == 0)
        val += (sx * sx + sy * sy) + (sz * sz + sw * sw);

    #pragma unroll
    for (int off = 16; off > 0; off >>= 1)
        val += __shfl_xor_sync(0xFFFFFFFFu, val, off);

    __shared__ float warp_sums[THREADS / 32];
    if (lane == 0) warp_sums[wid] = val;
    __syncthreads();

    // warp 0 finishes: 16 partials -> lane-parallel shfl tree -> one atomic
    if (wid == 0) {
        float blk = (lane < THREADS / 32) ? warp_sums[lane] : 0.f;
        #pragma unroll
        for (int off = 8; off > 0; off >>= 1)
            blk += __shfl_xor_sync(0xFFFFFFFFu, blk, off);
        if (lane == 0) {
            atomicAdd(&g_acc, (double)blk);
            __threadfence();
            unsigned int ticket = atomicAdd(&g_count, 1u);
            if (ticket == (unsigned int)nblocks - 1u) {
                out[0] = (float)(g_acc * inv_d);
                g_acc = 0.0;     // reset for next graph replay
                g_count = 0u;
            }
        }
    }
}

__global__ void __launch_bounds__(THREADS, 2)
ortho_fixed_kernel(const float4* __restrict__ in, float* __restrict__ out,
                   double inv_d, int nblocks) {
    ortho_body<D4_CONST>(in, out, inv_d, nblocks);
}

// Generic fallback (runtime d4), identical math.
__global__ void __launch_bounds__(256, 1)
ortho_generic_kernel(const float4* __restrict__ in, float* __restrict__ out,
                     int d4, double inv_d, int nblocks) {
    int idx = blockIdx.x * 256 + threadIdx.x;
    float s0 = 0.f, s1 = 0.f, s2 = 0.f, s3 = 0.f;
    float t0 = 0.f, t1 = 0.f, t2 = 0.f, t3 = 0.f;
    if (idx < d4) {
        #pragma unroll
        for (int b = 0; b < B_ROWS; b++) {
            float4 v = in[(size_t)b * d4 + idx];
            float a0 = v.x * v.x, a1 = v.y * v.y, a2 = v.z * v.z, a3 = v.w * v.w;
            s0 += a0; t0 = fmaf(a0, a0, t0);
            s1 += a1; t1 = fmaf(a1, a1, t1);
            s2 += a2; t2 = fmaf(a2, a2, t2);
            s3 += a3; t3 = fmaf(a3, a3, t3);
        }
    }
    float val = (fmaf(s0, s0, -t0) + fmaf(s1, s1, -t1))
              + (fmaf(s2, s2, -t2) + fmaf(s3, s3, -t3));
    #pragma unroll
    for (int off = 16; off > 0; off >>= 1)
        val += __shfl_xor_sync(0xFFFFFFFFu, val, off);
    __shared__ float ws[8];
    int lane = threadIdx.x & 31, wid = threadIdx.x >> 5;
    if (lane == 0) ws[wid] = val;
    __syncthreads();
    if (wid == 0) {
        float blk = (lane < 8) ? ws[lane] : 0.f;
        #pragma unroll
        for (int off = 4; off > 0; off >>= 1)
            blk += __shfl_xor_sync(0xFFFFFFFFu, blk, off);
        if (lane == 0) {
            atomicAdd(&g_acc, (double)blk);
            __threadfence();
            unsigned int ticket = atomicAdd(&g_count, 1u);
            if (ticket == (unsigned int)nblocks - 1u) {
                out[0] = (float)(g_acc * inv_d);
                g_acc = 0.0;
                g_count = 0u;
            }
        }
    }
}

extern "C" void kernel_launch(void* const* d_in, const int* in_sizes, int n_in,
                              void* d_out, int out_size) {
    const float4* in = (const float4*)d_in[0];
    float* out = (float*)d_out;

    int total = in_sizes[0];
    int D = total / B_ROWS;
    int d4 = D / 4;

    if (d4 == D4_CONST) {
        int blocks = D4_CONST / ((THREADS / 32) * 8);   // 294, exact
        ortho_fixed_kernel<<<blocks, THREADS>>>(in, out, 1.0 / (double)D, blocks);
    } else {
        int blocks = (d4 + 255) / 256;
        ortho_generic_kernel<<<blocks, 256>>>(in, out, d4, 1.0 / (double)D, blocks);
    }
}

// round 15
// speedup vs baseline: 1.0036x; 1.0036x over previous
#include <cuda_runtime.h>
#include <cuda_bf16.h>
#include <cstdint>

// Off-diagonal Gram sum via:
//   (1/D) sum_d [ (sum_b x2[b,d])^2 - sum_b x2[b,d]^2 ],  x2 = x*x.
//
// FINAL (converged): 294 CTAs x 512 thr (32 warps/SM), warp-internal
// 4-way b-split (lane = 8q + c), 8 staged LDG.128/thread at compile-
// time-constant strides, packed f32x2 inner math, shfl-only s-recombine,
// single fused kernel with last-block finalize.
//
// 14 rounds established: (a) a ~8.8 +/- 0.25us bench floor (graph-replay/
// launch overhead + clock-unramped hot phase at the per-SM memory
// request-rate cap — invariant to MLP depth, warps/SM, LDG.128/256, TMA);
// (b) identical binaries print 8.70-8.96us run-to-run. This config hit
// the 8.704 floor most often with the best cold profile (ncu 7.97us,
// DRAM 30.7%, occ 36%). Headline win was algebraic: restructuring the
// B x B Gram einsum into one O(B*D) streaming pass.

#define B_ROWS 32
#define THREADS 512
#define QROWS 8
#define D4_CONST 37632          // 150528 / 4

__device__ double g_acc = 0.0;
__device__ unsigned int g_count = 0;

__device__ __forceinline__ unsigned long long pk2(float lo, float hi) {
    unsigned long long r;
    asm("mov.b64 %0, {%1, %2};" : "=l"(r) : "f"(lo), "f"(hi));
    return r;
}
__device__ __forceinline__ void upk2(unsigned long long v, float& lo, float& hi) {
    asm("mov.b64 {%0, %1}, %2;" : "=f"(lo), "=f"(hi) : "l"(v));
}
__device__ __forceinline__ unsigned long long mul2(unsigned long long a, unsigned long long b) {
    unsigned long long r;
    asm("mul.rn.f32x2 %0, %1, %2;" : "=l"(r) : "l"(a), "l"(b));
    return r;
}
__device__ __forceinline__ unsigned long long add2(unsigned long long a, unsigned long long b) {
    unsigned long long r;
    asm("add.rn.f32x2 %0, %1, %2;" : "=l"(r) : "l"(a), "l"(b));
    return r;
}
__device__ __forceinline__ unsigned long long fma2(unsigned long long a, unsigned long long b,
                                                   unsigned long long c) {
    unsigned long long r;
    asm("fma.rn.f32x2 %0, %1, %2, %3;" : "=l"(r) : "l"(a), "l"(b), "l"(c));
    return r;
}

template <int D4>
__device__ __forceinline__ void ortho_body(const float4* __restrict__ in,
                                           float* __restrict__ out,
                                           double inv_d, int nblocks) {
    const int tid  = threadIdx.x;
    const int lane = tid & 31;
    const int q    = lane >> 3;                       // b-quarter 0..3
    const int c    = lane & 7;                        // column within warp
    const int wid  = tid >> 5;
    const int gw   = blockIdx.x * (THREADS / 32) + wid;
    const int col  = gw * 8 + c;

    // 8 staged loads at compile-time-constant offsets from one base
    const float4* p = in + (size_t)(q * QROWS) * D4 + col;
    float4 v[QROWS];
    #pragma unroll
    for (int j = 0; j < QROWS; j++)
        v[j] = p[(size_t)j * D4];

    unsigned long long s01 = 0ull, s23 = 0ull, t01 = 0ull, t23 = 0ull;
    #pragma unroll
    for (int j = 0; j < QROWS; j++) {
        unsigned long long v01 = pk2(v[j].x, v[j].y);
        unsigned long long v23 = pk2(v[j].z, v[j].w);
        unsigned long long a01 = mul2(v01, v01);
        unsigned long long a23 = mul2(v23, v23);
        s01 = add2(s01, a01);
        s23 = add2(s23, a23);
        t01 = fma2(a01, a01, t01);
        t23 = fma2(a23, a23, t23);
    }

    float sx, sy, sz, sw, tx, ty, tz, tw;
    upk2(s01, sx, sy); upk2(s23, sz, sw);
    upk2(t01, tx, ty); upk2(t23, tz, tw);
    float tsum = (tx + ty) + (tz + tw);

    // recombine s across the 4 b-quarters (lanes c, c+8, c+16, c+24)
    sx += __shfl_xor_sync(0xFFFFFFFFu, sx, 8);
    sx += __shfl_xor_sync(0xFFFFFFFFu, sx, 16);
    sy += __shfl_xor_sync(0xFFFFFFFFu, sy, 8);
    sy += __shfl_xor_sync(0xFFFFFFFFu, sy, 16);
    sz += __shfl_xor_sync(0xFFFFFFFFu, sz, 8);
    sz += __shfl_xor_sync(0xFFFFFFFFu, sz, 16);
    sw += __shfl_xor_sync(0xFFFFFFFFu, sw, 8);
    sw += __shfl_xor_sync(0xFFFFFFFFu, sw, 16);

    float val = -tsum;
    if (q == 0)
        val += (sx * sx + sy * sy) + (sz * sz + sw * sw);

    #pragma unroll
    for (int off = 16; off > 0; off >>= 1)
        val += __shfl_xor_sync(0xFFFFFFFFu, val, off);

    __shared__ float warp_sums[THREADS / 32];
    if (lane == 0) warp_sums[wid] = val;
    __syncthreads();

    // warp 0 finishes: 16 partials -> lane-parallel shfl tree -> one atomic
    if (wid == 0) {
        float blk = (lane < THREADS / 32) ? warp_sums[lane] : 0.f;
        #pragma unroll
        for (int off = 8; off > 0; off >>= 1)
            blk += __shfl_xor_sync(0xFFFFFFFFu, blk, off);
        if (lane == 0) {
            atomicAdd(&g_acc, (double)blk);
            __threadfence();
            unsigned int ticket = atomicAdd(&g_count, 1u);
            if (ticket == (unsigned int)nblocks - 1u) {
                out[0] = (float)(g_acc * inv_d);
                g_acc = 0.0;     // reset for next graph replay
                g_count = 0u;
            }
        }
    }
}

__global__ void __launch_bounds__(THREADS, 2)
ortho_fixed_kernel(const float4* __restrict__ in, float* __restrict__ out,
                   double inv_d, int nblocks) {
    ortho_body<D4_CONST>(in, out, inv_d, nblocks);
}

// Generic fallback (runtime d4), identical math.
__global__ void __launch_bounds__(256, 1)
ortho_generic_kernel(const float4* __restrict__ in, float* __restrict__ out,
                     int d4, double inv_d, int nblocks) {
    int idx = blockIdx.x * 256 + threadIdx.x;
    float s0 = 0.f, s1 = 0.f, s2 = 0.f, s3 = 0.f;
    float t0 = 0.f, t1 = 0.f, t2 = 0.f, t3 = 0.f;
    if (idx < d4) {
        #pragma unroll
        for (int b = 0; b < B_ROWS; b++) {
            float4 v = in[(size_t)b * d4 + idx];
            float a0 = v.x * v.x, a1 = v.y * v.y, a2 = v.z * v.z, a3 = v.w * v.w;
            s0 += a0; t0 = fmaf(a0, a0, t0);
            s1 += a1; t1 = fmaf(a1, a1, t1);
            s2 += a2; t2 = fmaf(a2, a2, t2);
            s3 += a3; t3 = fmaf(a3, a3, t3);
        }
    }
    float val = (fmaf(s0, s0, -t0) + fmaf(s1, s1, -t1))
              + (fmaf(s2, s2, -t2) + fmaf(s3, s3, -t3));
    #pragma unroll
    for (int off = 16; off > 0; off >>= 1)
        val += __shfl_xor_sync(0xFFFFFFFFu, val, off);
    __shared__ float ws[8];
    int lane = threadIdx.x & 31, wid = threadIdx.x >> 5;
    if (lane == 0) ws[wid] = val;
    __syncthreads();
    if (wid == 0) {
        float blk = (lane < 8) ? ws[lane] : 0.f;
        #pragma unroll
        for (int off = 4; off > 0; off >>= 1)
            blk += __shfl_xor_sync(0xFFFFFFFFu, blk, off);
        if (lane == 0) {
            atomicAdd(&g_acc, (double)blk);
            __threadfence();
            unsigned int ticket = atomicAdd(&g_count, 1u);
            if (ticket == (unsigned int)nblocks - 1u) {
                out[0] = (float)(g_acc * inv_d);
                g_acc = 0.0;
                g_count = 0u;
            }
        }
    }
}

extern "C" void kernel_launch(void* const* d_in, const int* in_sizes, int n_in,
                              void* d_out, int out_size) {
    const float4* in = (const float4*)d_in[0];
    float* out = (float*)d_out;

    int total = in_sizes[0];
    int D = total / B_ROWS;
    int d4 = D / 4;

    if (d4 == D4_CONST) {
        int blocks = D4_CONST / ((THREADS / 32) * 8);   // 294, exact
        ortho_fixed_kernel<<<blocks, THREADS>>>(in, out, 1.0 / (double)D, blocks);
    } else {
        int blocks = (d4 + 255) / 256;
        ortho_generic_kernel<<<blocks, 256>>>(in, out, d4, 1.0 / (double)D, blocks);
    }
}

// round 16
// speedup vs baseline: 1.0332x; 1.0295x over previous
#include <cuda_runtime.h>
#include <cuda_bf16.h>
#include <cstdint>

// Off-diagonal Gram sum via:
//   (1/D) sum_d [ (sum_b x2[b,d])^2 - sum_b x2[b,d]^2 ],  x2 = x*x.
//
// R16 (final probe): max per-thread MLP x min request count.
// 147 CTAs x 256 thr; thread (c, h) owns one 32B chunk (8 floats) across
// 16 b-rows (h splits b in half): 16 staged LDG.256 per thread
// (~128 data regs; 256-reg budget at 256 thr/CTA). s recombined via an
// 8KB smem pair-exchange (tid <-> tid+128); x^4 additive. Packed f32x2.

#define B_ROWS 32
#define THREADS 256
#define HROWS 16                 // b-rows per thread
#define D_CONST 150528
#define D8_CONST (D_CONST / 8)   // 18816 = 147 * 128

__device__ double g_acc = 0.0;
__device__ unsigned int g_count = 0;

typedef unsigned long long u64;

__device__ __forceinline__ void upk2(u64 v, float& lo, float& hi) {
    asm("mov.b64 {%0, %1}, %2;" : "=f"(lo), "=f"(hi) : "l"(v));
}
__device__ __forceinline__ u64 mul2(u64 a, u64 b) {
    u64 r; asm("mul.rn.f32x2 %0, %1, %2;" : "=l"(r) : "l"(a), "l"(b)); return r;
}
__device__ __forceinline__ u64 add2(u64 a, u64 b) {
    u64 r; asm("add.rn.f32x2 %0, %1, %2;" : "=l"(r) : "l"(a), "l"(b)); return r;
}
__device__ __forceinline__ u64 fma2(u64 a, u64 b, u64 c) {
    u64 r; asm("fma.rn.f32x2 %0, %1, %2, %3;" : "=l"(r) : "l"(a), "l"(b), "l"(c)); return r;
}

struct U256 { u64 a, b, c, d; };
__device__ __forceinline__ U256 ldg256(const float* p) {
    U256 r;
    asm volatile("ld.global.v4.b64 {%0, %1, %2, %3}, [%4];"
                 : "=l"(r.a), "=l"(r.b), "=l"(r.c), "=l"(r.d)
                 : "l"(p));
    return r;
}

__global__ void __launch_bounds__(THREADS, 1)
ortho_fixed_kernel(const float* __restrict__ in, float* __restrict__ out,
                   double inv_d, int nblocks) {
    const int tid  = threadIdx.x;
    const int c    = tid & 127;                        // chunk slot in CTA
    const int h    = tid >> 7;                         // b-half 0/1
    const int col8 = blockIdx.x * 128 + c;             // 147*128 = 18816 exact

    // 16 staged 256-bit loads: rows h*16 .. h*16+15, 8 consecutive floats.
    // 32B-aligned: col8*32 and row*D*4 (D%8==0) are multiples of 32.
    const float* p = in + (size_t)(h * HROWS) * D_CONST + (size_t)col8 * 8;
    U256 v[HROWS];
    #pragma unroll
    for (int j = 0; j < HROWS; j++)
        v[j] = ldg256(p + (size_t)j * D_CONST);

    u64 s0 = 0ull, s1 = 0ull, s2 = 0ull, s3 = 0ull;
    u64 t0 = 0ull, t1 = 0ull, t2 = 0ull, t3 = 0ull;
    #pragma unroll
    for (int j = 0; j < HROWS; j++) {
        u64 a0 = mul2(v[j].a, v[j].a);
        u64 a1 = mul2(v[j].b, v[j].b);
        u64 a2 = mul2(v[j].c, v[j].c);
        u64 a3 = mul2(v[j].d, v[j].d);
        s0 = add2(s0, a0); t0 = fma2(a0, a0, t0);
        s1 = add2(s1, a1); t1 = fma2(a1, a1, t1);
        s2 = add2(s2, a2); t2 = fma2(a2, a2, t2);
        s3 = add2(s3, a3); t3 = fma2(a3, a3, t3);
    }

    // local x^4 sum (additive across halves)
    float ta, tb, tsum = 0.f;
    upk2(t0, ta, tb); tsum += ta + tb;
    upk2(t1, ta, tb); tsum += ta + tb;
    upk2(t2, ta, tb); tsum += ta + tb;
    upk2(t3, ta, tb); tsum += ta + tb;

    // exchange partial s between the two b-halves of each chunk (8KB smem)
    __shared__ u64 spart[THREADS][4];
    spart[tid][0] = s0; spart[tid][1] = s1;
    spart[tid][2] = s2; spart[tid][3] = s3;
    __syncthreads();

    float val = -tsum;
    if (h == 0) {
        u64 f0 = add2(s0, spart[tid + 128][0]);
        u64 f1 = add2(s1, spart[tid + 128][1]);
        u64 f2 = add2(s2, spart[tid + 128][2]);
        u64 f3 = add2(s3, spart[tid + 128][3]);
        float x, y, ss = 0.f;
        upk2(f0, x, y); ss += x * x + y * y;
        upk2(f1, x, y); ss += x * x + y * y;
        upk2(f2, x, y); ss += x * x + y * y;
        upk2(f3, x, y); ss += x * x + y * y;
        val += ss;
    }

    #pragma unroll
    for (int off = 16; off > 0; off >>= 1)
        val += __shfl_xor_sync(0xFFFFFFFFu, val, off);

    __shared__ float warp_sums[THREADS / 32];
    int lane = tid & 31;
    int wid  = tid >> 5;
    if (lane == 0) warp_sums[wid] = val;
    __syncthreads();

    if (wid == 0) {
        float blk = (lane < THREADS / 32) ? warp_sums[lane] : 0.f;
        #pragma unroll
        for (int off = 4; off > 0; off >>= 1)
            blk += __shfl_xor_sync(0xFFFFFFFFu, blk, off);
        if (lane == 0) {
            atomicAdd(&g_acc, (double)blk);
            __threadfence();
            unsigned int ticket = atomicAdd(&g_count, 1u);
            if (ticket == (unsigned int)nblocks - 1u) {
                out[0] = (float)(g_acc * inv_d);
                g_acc = 0.0;     // reset for next graph replay
                g_count = 0u;
            }
        }
    }
}

// Generic fallback (runtime shape), identical math.
__global__ void __launch_bounds__(256, 1)
ortho_generic_kernel(const float4* __restrict__ in, float* __restrict__ out,
                     int d4, double inv_d, int nblocks) {
    int idx = blockIdx.x * 256 + threadIdx.x;
    float s0 = 0.f, s1 = 0.f, s2 = 0.f, s3 = 0.f;
    float t0 = 0.f, t1 = 0.f, t2 = 0.f, t3 = 0.f;
    if (idx < d4) {
        #pragma unroll
        for (int b = 0; b < B_ROWS; b++) {
            float4 v = in[(size_t)b * d4 + idx];
            float a0 = v.x * v.x, a1 = v.y * v.y, a2 = v.z * v.z, a3 = v.w * v.w;
            s0 += a0; t0 = fmaf(a0, a0, t0);
            s1 += a1; t1 = fmaf(a1, a1, t1);
            s2 += a2; t2 = fmaf(a2, a2, t2);
            s3 += a3; t3 = fmaf(a3, a3, t3);
        }
    }
    float val = (fmaf(s0, s0, -t0) + fmaf(s1, s1, -t1))
              + (fmaf(s2, s2, -t2) + fmaf(s3, s3, -t3));
    #pragma unroll
    for (int off = 16; off > 0; off >>= 1)
        val += __shfl_xor_sync(0xFFFFFFFFu, val, off);
    __shared__ float ws[8];
    int lane = threadIdx.x & 31, wid = threadIdx.x >> 5;
    if (lane == 0) ws[wid] = val;
    __syncthreads();
    if (wid == 0) {
        float blk = (lane < 8) ? ws[lane] : 0.f;
        #pragma unroll
        for (int off = 4; off > 0; off >>= 1)
            blk += __shfl_xor_sync(0xFFFFFFFFu, blk, off);
        if (lane == 0) {
            atomicAdd(&g_acc, (double)blk);
            __threadfence();
            unsigned int ticket = atomicAdd(&g_count, 1u);
            if (ticket == (unsigned int)nblocks - 1u) {
                out[0] = (float)(g_acc * inv_d);
                g_acc = 0.0;
                g_count = 0u;
            }
        }
    }
}

extern "C" void kernel_launch(void* const* d_in, const int* in_sizes, int n_in,
                              void* d_out, int out_size) {
    int total = in_sizes[0];
    int D = total / B_ROWS;

    if (D == D_CONST) {
        int blocks = D8_CONST / 128;   // 147, exact
        ortho_fixed_kernel<<<blocks, THREADS>>>((const float*)d_in[0], (float*)d_out,
                                                1.0 / (double)D, blocks);
    } else {
        int d4 = D / 4;
        int blocks = (d4 + 255) / 256;
        ortho_generic_kernel<<<blocks, 256>>>((const float4*)d_in[0], (float*)d_out,
                                              d4, 1.0 / (double)D, blocks);
    }
}